// round 15
// baseline (speedup 1.0000x reference)
#include <cuda_runtime.h>
#include <cuda_fp16.h>
#include <math.h>

#define N_NODES 100000
#define N_EDGES 1600000
#define NB_SCAN 391   // ceil(100000/256)

// ---------------- scratch (device globals) ----------------
__device__ float  g_h1[(size_t)N_NODES * 64];   // tanh MLP branch (fp32)
__device__ __half g_xs[(size_t)N_NODES * 64];   // filter linear out (UNscaled, fp16)
__device__ float  g_h2[(size_t)N_NODES * 64];   // aggregated branch (inv_in applied)
__device__ int    g_deg_out[N_NODES];
__device__ int    g_deg_in [N_NODES];
__device__ float  g_inv_out[N_NODES];
__device__ int    g_rowstart[N_NODES];
__device__ int    g_cursor[N_NODES];
__device__ int    g_part[512];
__device__ int    g_csr[N_EDGES];
__device__ float  g_W[64 * 128];                // fused [k][j]: j<64 fc1, j>=64 filt
__device__ float  g_bias[128];
__device__ float  g_wpart[2][16];               // attention logit partial sums

__device__ __forceinline__ float fast_tanh(float x) {
    float e = __expf(2.f * x);
    return 1.f - __fdividef(2.f, e + 1.f);
}

// ---- packed f32x2 helpers (sm_103a) ----
__device__ __forceinline__ unsigned long long pack2(float lo, float hi) {
    unsigned long long r;
    asm("mov.b64 %0, {%1, %2};" : "=l"(r) : "f"(lo), "f"(hi));
    return r;
}
__device__ __forceinline__ float2 unpack2(unsigned long long v) {
    float2 r;
    asm("mov.b64 {%0, %1}, %2;" : "=f"(r.x), "=f"(r.y) : "l"(v));
    return r;
}
__device__ __forceinline__ void fma2(unsigned long long& d, unsigned long long a,
                                     unsigned long long b) {
    asm("fma.rn.f32x2 %0, %1, %2, %0;" : "+l"(d) : "l"(a), "l"(b));
}

// ---------------- zero scratch ----------------
__global__ void k_init() {
    int i = blockIdx.x * blockDim.x + threadIdx.x;
    if (i < N_NODES) { g_deg_out[i] = 0; g_deg_in[i] = 0; }
    if (i < 32) g_wpart[i >> 4][i & 15] = 0.f;
}

// ---------------- degree histogram (4 edges / thread) ----------------
__global__ void k_degree(const int4* __restrict__ src4, const int4* __restrict__ dst4) {
    int i = blockIdx.x * blockDim.x + threadIdx.x;
    if (i >= N_EDGES / 4) return;
    int4 s = __ldg(&src4[i]);
    int4 d = __ldg(&dst4[i]);
    atomicAdd(&g_deg_out[s.x], 1); atomicAdd(&g_deg_out[s.y], 1);
    atomicAdd(&g_deg_out[s.z], 1); atomicAdd(&g_deg_out[s.w], 1);
    atomicAdd(&g_deg_in[d.x], 1);  atomicAdd(&g_deg_in[d.y], 1);
    atomicAdd(&g_deg_in[d.z], 1);  atomicAdd(&g_deg_in[d.w], 1);
}

// ---------------- weight prep (no degree dependency) ----------------
__global__ void k_prepW(const float* __restrict__ fc1_w, const float* __restrict__ fc1_b,
                        const float* __restrict__ filt_w, const float* __restrict__ filt_b) {
    int i = blockIdx.x * blockDim.x + threadIdx.x;
    if (i < 64 * 128) {
        int k = i >> 7, j = i & 127;
        g_W[i] = (j < 64) ? fc1_w[j * 64 + k] : filt_w[(j - 64) * 64 + k];
    }
    if (i < 128) g_bias[i] = (i < 64) ? fc1_b[i] : filt_b[i - 64];
}

// ---------------- exclusive scan of deg_in (inv_out folded into stage 3) --------
__global__ void k_scan1() {
    __shared__ int sh[256];
    int t = threadIdx.x;
    int i = blockIdx.x * 256 + t;
    int v = (i < N_NODES) ? g_deg_in[i] : 0;
    sh[t] = v;
    __syncthreads();
#pragma unroll
    for (int off = 1; off < 256; off <<= 1) {
        int add = (t >= off) ? sh[t - off] : 0;
        __syncthreads();
        sh[t] += add;
        __syncthreads();
    }
    if (i < N_NODES) g_rowstart[i] = sh[t] - v;
    if (t == 255) g_part[blockIdx.x] = sh[255];
}

__global__ void k_scan2() {
    __shared__ int sh[512];
    int t = threadIdx.x;
    int v = (t < NB_SCAN) ? g_part[t] : 0;
    sh[t] = v;
    __syncthreads();
#pragma unroll
    for (int off = 1; off < 512; off <<= 1) {
        int add = (t >= off) ? sh[t - off] : 0;
        __syncthreads();
        sh[t] += add;
        __syncthreads();
    }
    if (t < NB_SCAN) g_part[t] = sh[t] - v;
}

__global__ void k_scan3() {
    int i = blockIdx.x * blockDim.x + threadIdx.x;
    if (i < N_NODES) {
        int rs = g_rowstart[i] + g_part[i >> 8];
        g_rowstart[i] = rs;
        g_cursor[i]   = rs;
        g_inv_out[i]  = rsqrtf(fmaxf((float)g_deg_out[i], 1.f));
    }
}

// ---------------- CSR build (counting sort by dst) ----------------
__global__ void k_csr(const int* __restrict__ src, const int* __restrict__ dst) {
    int e = blockIdx.x * blockDim.x + threadIdx.x;
    if (e >= N_EDGES) return;
    int d = __ldg(&dst[e]);
    int pos = atomicAdd(&g_cursor[d], 1);
    g_csr[pos] = __ldg(&src[e]);
}

// ---------------- half GEMM A: xs = feat @ filt_w^T + b (fp16, UNscaled) ----------------
// 256 threads, block tile 256 nodes x 64 cols, thread tile 8x8 (f32x2 pairs)
__global__ __launch_bounds__(256) void k_gemm_xs(const float* __restrict__ feat) {
    __shared__ float Bs[64 * 68];    // filt weights [k][j], padded rows
    __shared__ float As[8 * 256];    // feat chunk transposed
    __shared__ float bias_s[64];

    int tid = threadIdx.x;
    int m0 = blockIdx.x * 256;

    for (int i = tid; i < 64 * 64; i += 256) {
        int k = i >> 6, j = i & 63;
        Bs[k * 68 + j] = g_W[k * 128 + 64 + j];
    }
    if (tid < 64) bias_s[tid] = g_bias[64 + tid];

    int tx = tid & 7, ty = tid >> 3;   // 8 col-groups of 8, 32 node-groups of 8

    unsigned long long acc[8][4];
#pragma unroll
    for (int i = 0; i < 8; i++)
#pragma unroll
        for (int j = 0; j < 4; j++) acc[i][j] = 0ull;

    int m_load = m0 + tid;
    bool valid = m_load < N_NODES;
    const float4* frow = reinterpret_cast<const float4*>(feat + (size_t)m_load * 64);
    float4 z4 = make_float4(0.f, 0.f, 0.f, 0.f);

    for (int kc = 0; kc < 64; kc += 8) {
        __syncthreads();
        float4 v0 = valid ? frow[kc >> 2]       : z4;
        float4 v1 = valid ? frow[(kc >> 2) + 1] : z4;
        As[0 * 256 + tid] = v0.x; As[1 * 256 + tid] = v0.y;
        As[2 * 256 + tid] = v0.z; As[3 * 256 + tid] = v0.w;
        As[4 * 256 + tid] = v1.x; As[5 * 256 + tid] = v1.y;
        As[6 * 256 + tid] = v1.z; As[7 * 256 + tid] = v1.w;
        __syncthreads();

#pragma unroll
        for (int k = 0; k < 8; k++) {
            float4 a0 = *reinterpret_cast<const float4*>(&As[k * 256 + ty * 8]);
            float4 a1 = *reinterpret_cast<const float4*>(&As[k * 256 + ty * 8 + 4]);
            const float* brow = &Bs[(kc + k) * 68 + tx * 8];
            ulonglong2 b01 = *reinterpret_cast<const ulonglong2*>(brow);
            ulonglong2 b23 = *reinterpret_cast<const ulonglong2*>(brow + 4);
            float a[8] = {a0.x, a0.y, a0.z, a0.w, a1.x, a1.y, a1.z, a1.w};
            unsigned long long bp[4] = {b01.x, b01.y, b23.x, b23.y};
#pragma unroll
            for (int i = 0; i < 8; i++) {
                unsigned long long ai = pack2(a[i], a[i]);
#pragma unroll
                for (int j = 0; j < 4; j++) fma2(acc[i][j], ai, bp[j]);
            }
        }
    }

    int jb = tx * 8;
#pragma unroll
    for (int i = 0; i < 8; i++) {
        int m = m0 + ty * 8 + i;
        if (m >= N_NODES) continue;
        union { __half2 h[4]; uint4 u; } pk;
#pragma unroll
        for (int p = 0; p < 4; p++) {
            float2 q = unpack2(acc[i][p]);
            pk.h[p] = __floats2half2_rn(q.x + bias_s[jb + 2 * p],
                                        q.y + bias_s[jb + 2 * p + 1]);
        }
        *reinterpret_cast<uint4*>(g_xs + (size_t)m * 64 + jb) = pk.u;
    }
}

// ---------------- half GEMM B: h1 = tanh(feat @ fc1_w^T + b) (fp32) ----------------
__global__ __launch_bounds__(256) void k_gemm_h1(const float* __restrict__ feat) {
    __shared__ float Bs[64 * 68];
    __shared__ float As[8 * 256];
    __shared__ float bias_s[64];

    int tid = threadIdx.x;
    int m0 = blockIdx.x * 256;

    for (int i = tid; i < 64 * 64; i += 256) {
        int k = i >> 6, j = i & 63;
        Bs[k * 68 + j] = g_W[k * 128 + j];
    }
    if (tid < 64) bias_s[tid] = g_bias[tid];

    int tx = tid & 7, ty = tid >> 3;

    unsigned long long acc[8][4];
#pragma unroll
    for (int i = 0; i < 8; i++)
#pragma unroll
        for (int j = 0; j < 4; j++) acc[i][j] = 0ull;

    int m_load = m0 + tid;
    bool valid = m_load < N_NODES;
    const float4* frow = reinterpret_cast<const float4*>(feat + (size_t)m_load * 64);
    float4 z4 = make_float4(0.f, 0.f, 0.f, 0.f);

    for (int kc = 0; kc < 64; kc += 8) {
        __syncthreads();
        float4 v0 = valid ? frow[kc >> 2]       : z4;
        float4 v1 = valid ? frow[(kc >> 2) + 1] : z4;
        As[0 * 256 + tid] = v0.x; As[1 * 256 + tid] = v0.y;
        As[2 * 256 + tid] = v0.z; As[3 * 256 + tid] = v0.w;
        As[4 * 256 + tid] = v1.x; As[5 * 256 + tid] = v1.y;
        As[6 * 256 + tid] = v1.z; As[7 * 256 + tid] = v1.w;
        __syncthreads();

#pragma unroll
        for (int k = 0; k < 8; k++) {
            float4 a0 = *reinterpret_cast<const float4*>(&As[k * 256 + ty * 8]);
            float4 a1 = *reinterpret_cast<const float4*>(&As[k * 256 + ty * 8 + 4]);
            const float* brow = &Bs[(kc + k) * 68 + tx * 8];
            ulonglong2 b01 = *reinterpret_cast<const ulonglong2*>(brow);
            ulonglong2 b23 = *reinterpret_cast<const ulonglong2*>(brow + 4);
            float a[8] = {a0.x, a0.y, a0.z, a0.w, a1.x, a1.y, a1.z, a1.w};
            unsigned long long bp[4] = {b01.x, b01.y, b23.x, b23.y};
#pragma unroll
            for (int i = 0; i < 8; i++) {
                unsigned long long ai = pack2(a[i], a[i]);
#pragma unroll
                for (int j = 0; j < 4; j++) fma2(acc[i][j], ai, bp[j]);
            }
        }
    }

    int jb = tx * 8;
#pragma unroll
    for (int i = 0; i < 8; i++) {
        int m = m0 + ty * 8 + i;
        if (m >= N_NODES) continue;
        float o[8];
#pragma unroll
        for (int p = 0; p < 4; p++) {
            float2 q = unpack2(acc[i][p]);
            o[2 * p]     = fast_tanh(q.x + bias_s[jb + 2 * p]);
            o[2 * p + 1] = fast_tanh(q.y + bias_s[jb + 2 * p + 1]);
        }
        float4* p = reinterpret_cast<float4*>(g_h1 + (size_t)m * 64 + jb);
        p[0] = make_float4(o[0], o[1], o[2], o[3]);
        p[1] = make_float4(o[4], o[5], o[6], o[7]);
    }
}

// ---------------- warp-per-node CSR aggregation (plain) ----------------
__global__ __launch_bounds__(256) void k_agg() {
    int tid = threadIdx.x;
    int warp = tid >> 5, lane = tid & 31;
    int n = blockIdx.x * 8 + warp;
    if (n >= N_NODES) return;

    int beg = g_rowstart[n];
    int deg = g_deg_in[n];
    int end = beg + deg;

    float2 acc = make_float2(0.f, 0.f);
    const __half2* xsh = reinterpret_cast<const __half2*>(g_xs);
    int e = beg;
    int end8 = beg + (deg & ~7);
    for (; e < end8; e += 8) {
        int s[8];
#pragma unroll
        for (int u = 0; u < 8; u++) s[u] = __ldg(&g_csr[e + u]);
        float w[8];
#pragma unroll
        for (int u = 0; u < 8; u++) w[u] = __ldg(&g_inv_out[s[u]]);
        float2 f[8];
#pragma unroll
        for (int u = 0; u < 8; u++)
            f[u] = __half22float2(__ldg(&xsh[(size_t)s[u] * 32 + lane]));
#pragma unroll
        for (int u = 0; u < 8; u++) {
            acc.x = fmaf(f[u].x, w[u], acc.x);
            acc.y = fmaf(f[u].y, w[u], acc.y);
        }
    }
    for (; e < end; e++) {
        int s0 = __ldg(&g_csr[e]);
        float w0 = __ldg(&g_inv_out[s0]);
        float2 f0 = __half22float2(__ldg(&xsh[(size_t)s0 * 32 + lane]));
        acc.x = fmaf(f0.x, w0, acc.x);
        acc.y = fmaf(f0.y, w0, acc.y);
    }
    float sc = rsqrtf(fmaxf((float)deg, 1.f));
    acc.x *= sc; acc.y *= sc;
    reinterpret_cast<float2*>(g_h2)[(size_t)n * 32 + lane] = acc;
}

// ---------------- attention logit sums (channel passed as arg) ----------------
__global__ __launch_bounds__(128) void k_att(const float* __restrict__ att_w1,
                                             const float* __restrict__ att_b1,
                                             const float* __restrict__ att_w2,
                                             int ch) {
    __shared__ float Ws[64][32];
    __shared__ float As[8][128];
    __shared__ float b1s[32], w2s[32];
    __shared__ float redbuf[4];

    int tid = threadIdx.x;
    int m0  = blockIdx.x * 128;

    for (int i = tid; i < 64 * 32; i += 128) ((float*)Ws)[i] = att_w1[i];
    if (tid < 32) { b1s[tid] = att_b1[tid]; w2s[tid] = att_w2[tid]; }

    int tx = tid & 7, ty = tid >> 3;
    const float* hsrc = ch ? g_h2 : g_h1;

    int m_load = m0 + tid;
    bool valid = m_load < N_NODES;
    const float4* hrow = reinterpret_cast<const float4*>(hsrc + (size_t)m_load * 64);
    float4 z4 = make_float4(0.f, 0.f, 0.f, 0.f);

    float acc[8][4];
#pragma unroll
    for (int i = 0; i < 8; i++)
#pragma unroll
        for (int j = 0; j < 4; j++) acc[i][j] = 0.f;

    for (int kc = 0; kc < 64; kc += 8) {
        __syncthreads();
        float4 v0 = valid ? hrow[kc >> 2]       : z4;
        float4 v1 = valid ? hrow[(kc >> 2) + 1] : z4;
        As[0][tid] = v0.x; As[1][tid] = v0.y; As[2][tid] = v0.z; As[3][tid] = v0.w;
        As[4][tid] = v1.x; As[5][tid] = v1.y; As[6][tid] = v1.z; As[7][tid] = v1.w;
        __syncthreads();

#pragma unroll
        for (int k = 0; k < 8; k++) {
            float4 a0 = *reinterpret_cast<const float4*>(&As[k][ty * 8]);
            float4 a1 = *reinterpret_cast<const float4*>(&As[k][ty * 8 + 4]);
            float4 b  = *reinterpret_cast<const float4*>(&Ws[kc + k][tx * 4]);
            float a[8] = {a0.x, a0.y, a0.z, a0.w, a1.x, a1.y, a1.z, a1.w};
            float bb[4] = {b.x, b.y, b.z, b.w};
#pragma unroll
            for (int i = 0; i < 8; i++)
#pragma unroll
                for (int j = 0; j < 4; j++) acc[i][j] += a[i] * bb[j];
        }
    }

    float part = 0.f;
#pragma unroll
    for (int i = 0; i < 8; i++) {
        int m = m0 + ty * 8 + i;
        if (m >= N_NODES) continue;
#pragma unroll
        for (int j = 0; j < 4; j++)
            part += fast_tanh(acc[i][j] + b1s[tx * 4 + j]) * w2s[tx * 4 + j];
    }
#pragma unroll
    for (int off = 16; off > 0; off >>= 1)
        part += __shfl_down_sync(0xffffffff, part, off);
    if ((tid & 31) == 0) redbuf[tid >> 5] = part;
    __syncthreads();
    if (tid == 0)
        atomicAdd(&g_wpart[ch][blockIdx.x & 15],
                  redbuf[0] + redbuf[1] + redbuf[2] + redbuf[3]);
}

// ---------------- final: beta softmax, blend, fc2 ----------------
__global__ __launch_bounds__(256) void k_out(const float* __restrict__ fc2_w,
                                             const float* __restrict__ fc2_b,
                                             float* __restrict__ out) {
    __shared__ float4 ws[16 * 16];
    __shared__ float bs[16];

    int tid = threadIdx.x;
    for (int i = tid; i < 16 * 16; i += 256)
        ws[i] = reinterpret_cast<const float4*>(fc2_w)[i];
    if (tid < 16) bs[tid] = fc2_b[tid];
    __syncthreads();

    int n = blockIdx.x * blockDim.x + tid;
    if (n >= N_NODES) return;

    float s0 = 0.f, s1 = 0.f;
#pragma unroll
    for (int i = 0; i < 16; i++) { s0 += g_wpart[0][i]; s1 += g_wpart[1][i]; }
    float m0 = s0 * (1.f / N_NODES);
    float m1 = s1 * (1.f / N_NODES);
    float mx = fmaxf(m0, m1);
    float e0 = expf(m0 - mx), e1 = expf(m1 - mx);
    float inv = 1.f / (e0 + e1);
    float b0 = e0 * inv, b1 = e1 * inv;

    const float4* r1 = reinterpret_cast<const float4*>(g_h1 + (size_t)n * 64);
    const float4* r2 = reinterpret_cast<const float4*>(g_h2 + (size_t)n * 64);
    float4 f[16];
#pragma unroll
    for (int i = 0; i < 16; i++) {
        float4 a = r1[i], b = r2[i];
        f[i] = make_float4(b0 * a.x + b1 * b.x, b0 * a.y + b1 * b.y,
                           b0 * a.z + b1 * b.z, b0 * a.w + b1 * b.w);
    }
    float o[16];
#pragma unroll
    for (int j = 0; j < 16; j++) {
        float acc = bs[j];
#pragma unroll
        for (int i = 0; i < 16; i++) {
            float4 w = ws[j * 16 + i];
            acc += f[i].x * w.x + f[i].y * w.y + f[i].z * w.z + f[i].w * w.w;
        }
        o[j] = acc;
    }
    float4* orow = reinterpret_cast<float4*>(out + (size_t)n * 16);
#pragma unroll
    for (int j = 0; j < 4; j++)
        orow[j] = make_float4(o[j * 4], o[j * 4 + 1], o[j * 4 + 2], o[j * 4 + 3]);
}

// ---------------- launch: split-gemm fork-join, agg gated only on xs ----------------
extern "C" void kernel_launch(void* const* d_in, const int* in_sizes, int n_in,
                              void* d_out, int out_size)
{
    const float* feat   = (const float*)d_in[0];
    const int*   e_src  = (const int*)  d_in[1];
    const int*   e_dst  = (const int*)  d_in[2];
    const float* fc1_w  = (const float*)d_in[3];
    const float* fc1_b  = (const float*)d_in[4];
    const float* filt_w = (const float*)d_in[5];
    const float* filt_b = (const float*)d_in[6];
    const float* att_w1 = (const float*)d_in[7];
    const float* att_b1 = (const float*)d_in[8];
    const float* att_w2 = (const float*)d_in[9];
    const float* fc2_w  = (const float*)d_in[10];
    const float* fc2_b  = (const float*)d_in[11];
    float* out = (float*)d_out;

    static cudaStream_t s1 = nullptr;
    static cudaEvent_t ev_fork = nullptr, ev_xs = nullptr, ev_s1 = nullptr;
    if (!s1) {
        cudaStreamCreateWithFlags(&s1, cudaStreamNonBlocking);
        cudaEventCreateWithFlags(&ev_fork, cudaEventDisableTiming);
        cudaEventCreateWithFlags(&ev_xs,   cudaEventDisableTiming);
        cudaEventCreateWithFlags(&ev_s1,   cudaEventDisableTiming);
    }
    cudaStream_t s0 = (cudaStream_t)0;

    // s0: init (zeroes degrees + wpart); fork point for s1
    k_init<<<(N_NODES + 255) / 256, 256, 0, s0>>>();
    cudaEventRecord(ev_fork, s0);

    // s1: weights -> xs half-GEMM (releases agg gate early) -> h1 half-GEMM -> ch-0 att
    cudaStreamWaitEvent(s1, ev_fork, 0);
    k_prepW<<<(64 * 128 + 255) / 256, 256, 0, s1>>>(fc1_w, fc1_b, filt_w, filt_b);
    k_gemm_xs<<<(N_NODES + 255) / 256, 256, 0, s1>>>(feat);
    cudaEventRecord(ev_xs, s1);
    k_gemm_h1<<<(N_NODES + 255) / 256, 256, 0, s1>>>(feat);
    k_att<<<(N_NODES + 127) / 128, 128, 0, s1>>>(att_w1, att_b1, att_w2, 0);
    cudaEventRecord(ev_s1, s1);

    // s0: graph chain — degrees -> scan(+inv_out) -> CSR (overlaps s1)
    k_degree<<<(N_EDGES / 4 + 255) / 256, 256, 0, s0>>>((const int4*)e_src, (const int4*)e_dst);
    k_scan1<<<NB_SCAN, 256, 0, s0>>>();
    k_scan2<<<1, 512, 0, s0>>>();
    k_scan3<<<(N_NODES + 255) / 256, 256, 0, s0>>>();
    k_csr<<<(N_EDGES + 255) / 256, 256, 0, s0>>>(e_src, e_dst);

    // join: aggregation needs CSR+inv_out (s0) and xs only (s1 early event)
    cudaStreamWaitEvent(s0, ev_xs, 0);
    k_agg<<<(N_NODES + 7) / 8, 256, 0, s0>>>();

    // ch-1 attention on h2 (overlaps s1's h1 gemm + ch-0 attention)
    k_att<<<(N_NODES + 127) / 128, 128, 0, s0>>>(att_w1, att_b1, att_w2, 1);

    // blend + fc2 (needs h1 + ch-0 logits from s1)
    cudaStreamWaitEvent(s0, ev_s1, 0);
    k_out<<<(N_NODES + 255) / 256, 256, 0, s0>>>(fc2_w, fc2_b, out);
}

// round 16
// speedup vs baseline: 1.0723x; 1.0723x over previous
#include <cuda_runtime.h>
#include <cuda_fp16.h>
#include <math.h>

#define N_NODES 100000
#define N_EDGES 1600000
#define NB_SCAN 391   // ceil(100000/256)

// ---------------- scratch (device globals) ----------------
__device__ float  g_h1[(size_t)N_NODES * 64];   // tanh MLP branch (fp32)
__device__ __half g_xs[(size_t)N_NODES * 64];   // filter linear out (UNscaled, fp16)
__device__ float  g_h2[(size_t)N_NODES * 64];   // aggregated branch (inv_in applied)
__device__ int    g_deg_out[N_NODES];
__device__ int    g_deg_in [N_NODES];
__device__ float  g_inv_out[N_NODES];
__device__ int    g_rowstart[N_NODES];
__device__ int    g_cursor[N_NODES];
__device__ int    g_part[512];
__device__ int    g_csr[N_EDGES];
__device__ float  g_W[64 * 128];                // fused [k][j]: j<64 fc1, j>=64 filt
__device__ float  g_bias[128];
__device__ float  g_wpart[2][16];               // attention logit partial sums

__device__ __forceinline__ float fast_tanh(float x) {
    float e = __expf(2.f * x);
    return 1.f - __fdividef(2.f, e + 1.f);
}

// ---- packed f32x2 helpers (sm_103a) ----
__device__ __forceinline__ unsigned long long pack2(float lo, float hi) {
    unsigned long long r;
    asm("mov.b64 %0, {%1, %2};" : "=l"(r) : "f"(lo), "f"(hi));
    return r;
}
__device__ __forceinline__ float2 unpack2(unsigned long long v) {
    float2 r;
    asm("mov.b64 {%0, %1}, %2;" : "=f"(r.x), "=f"(r.y) : "l"(v));
    return r;
}
__device__ __forceinline__ void fma2(unsigned long long& d, unsigned long long a,
                                     unsigned long long b) {
    asm("fma.rn.f32x2 %0, %1, %2, %0;" : "+l"(d) : "l"(a), "l"(b));
}

// ---------------- zero scratch ----------------
__global__ void k_init() {
    int i = blockIdx.x * blockDim.x + threadIdx.x;
    if (i < N_NODES) { g_deg_out[i] = 0; g_deg_in[i] = 0; }
    if (i < 32) g_wpart[i >> 4][i & 15] = 0.f;
}

// ---------------- degree histogram (4 edges / thread) ----------------
__global__ void k_degree(const int4* __restrict__ src4, const int4* __restrict__ dst4) {
    int i = blockIdx.x * blockDim.x + threadIdx.x;
    if (i >= N_EDGES / 4) return;
    int4 s = __ldg(&src4[i]);
    int4 d = __ldg(&dst4[i]);
    atomicAdd(&g_deg_out[s.x], 1); atomicAdd(&g_deg_out[s.y], 1);
    atomicAdd(&g_deg_out[s.z], 1); atomicAdd(&g_deg_out[s.w], 1);
    atomicAdd(&g_deg_in[d.x], 1);  atomicAdd(&g_deg_in[d.y], 1);
    atomicAdd(&g_deg_in[d.z], 1);  atomicAdd(&g_deg_in[d.w], 1);
}

// ---------------- weight prep (no degree dependency) ----------------
__global__ void k_prepW(const float* __restrict__ fc1_w, const float* __restrict__ fc1_b,
                        const float* __restrict__ filt_w, const float* __restrict__ filt_b) {
    int i = blockIdx.x * blockDim.x + threadIdx.x;
    if (i < 64 * 128) {
        int k = i >> 7, j = i & 127;
        g_W[i] = (j < 64) ? fc1_w[j * 64 + k] : filt_w[(j - 64) * 64 + k];
    }
    if (i < 128) g_bias[i] = (i < 64) ? fc1_b[i] : filt_b[i - 64];
}

// ---------------- exclusive scan of deg_in (inv_out folded into stage 3) --------
__global__ void k_scan1() {
    __shared__ int sh[256];
    int t = threadIdx.x;
    int i = blockIdx.x * 256 + t;
    int v = (i < N_NODES) ? g_deg_in[i] : 0;
    sh[t] = v;
    __syncthreads();
#pragma unroll
    for (int off = 1; off < 256; off <<= 1) {
        int add = (t >= off) ? sh[t - off] : 0;
        __syncthreads();
        sh[t] += add;
        __syncthreads();
    }
    if (i < N_NODES) g_rowstart[i] = sh[t] - v;
    if (t == 255) g_part[blockIdx.x] = sh[255];
}

__global__ void k_scan2() {
    __shared__ int sh[512];
    int t = threadIdx.x;
    int v = (t < NB_SCAN) ? g_part[t] : 0;
    sh[t] = v;
    __syncthreads();
#pragma unroll
    for (int off = 1; off < 512; off <<= 1) {
        int add = (t >= off) ? sh[t - off] : 0;
        __syncthreads();
        sh[t] += add;
        __syncthreads();
    }
    if (t < NB_SCAN) g_part[t] = sh[t] - v;
}

__global__ void k_scan3() {
    int i = blockIdx.x * blockDim.x + threadIdx.x;
    if (i < N_NODES) {
        int rs = g_rowstart[i] + g_part[i >> 8];
        g_rowstart[i] = rs;
        g_cursor[i]   = rs;
        g_inv_out[i]  = rsqrtf(fmaxf((float)g_deg_out[i], 1.f));
    }
}

// ---------------- CSR build (counting sort by dst) ----------------
__global__ void k_csr(const int* __restrict__ src, const int* __restrict__ dst) {
    int e = blockIdx.x * blockDim.x + threadIdx.x;
    if (e >= N_EDGES) return;
    int d = __ldg(&dst[e]);
    int pos = atomicAdd(&g_cursor[d], 1);
    g_csr[pos] = __ldg(&src[e]);
}

// ---------------- tiled dual GEMM + FUSED ch-0 attention (R14 config) ----------------
__global__ __launch_bounds__(256) void k_gemm(const float* __restrict__ feat,
                                              const float* __restrict__ att_w1,
                                              const float* __restrict__ att_b1,
                                              const float* __restrict__ att_w2) {
    __shared__ float SM[10752];
    __shared__ float bias_s[128];
    __shared__ float b1s[32], w2s[32];
    __shared__ float redbuf[8];

    float* Bs = SM;            // [64][128] during main loop
    float* As = SM + 8192;     // [16][128] during main loop

    int tid = threadIdx.x;
    int m0 = blockIdx.x * 128;

    for (int i = tid; i < 64 * 128; i += 256) Bs[i] = g_W[i];
    if (tid < 128) bias_s[tid] = g_bias[tid];
    if (tid < 32) { b1s[tid] = att_b1[tid]; w2s[tid] = att_w2[tid]; }

    int tx = tid & 15, ty = tid >> 4;
    int r  = tid & 127, hf = tid >> 7;

    unsigned long long acc[8][4];
#pragma unroll
    for (int i = 0; i < 8; i++)
#pragma unroll
        for (int j = 0; j < 4; j++) acc[i][j] = 0ull;

    int m_load = m0 + r;
    bool valid = m_load < N_NODES;
    const float4* frow = reinterpret_cast<const float4*>(feat + (size_t)m_load * 64);
    float4 z4 = make_float4(0.f, 0.f, 0.f, 0.f);

    for (int kc = 0; kc < 64; kc += 16) {
        __syncthreads();
        float4 v0 = valid ? frow[(kc >> 2) + hf * 2]     : z4;
        float4 v1 = valid ? frow[(kc >> 2) + hf * 2 + 1] : z4;
        int kb = hf * 8;
        As[(kb + 0) * 128 + r] = v0.x; As[(kb + 1) * 128 + r] = v0.y;
        As[(kb + 2) * 128 + r] = v0.z; As[(kb + 3) * 128 + r] = v0.w;
        As[(kb + 4) * 128 + r] = v1.x; As[(kb + 5) * 128 + r] = v1.y;
        As[(kb + 6) * 128 + r] = v1.z; As[(kb + 7) * 128 + r] = v1.w;
        __syncthreads();

#pragma unroll
        for (int k = 0; k < 16; k++) {
            float4 a0 = *reinterpret_cast<const float4*>(&As[k * 128 + ty * 8]);
            float4 a1 = *reinterpret_cast<const float4*>(&As[k * 128 + ty * 8 + 4]);
            ulonglong2 b01 = *reinterpret_cast<const ulonglong2*>(&Bs[(kc + k) * 128 + tx * 8]);
            ulonglong2 b23 = *reinterpret_cast<const ulonglong2*>(&Bs[(kc + k) * 128 + tx * 8 + 4]);
            float a[8] = {a0.x, a0.y, a0.z, a0.w, a1.x, a1.y, a1.z, a1.w};
            unsigned long long bp[4] = {b01.x, b01.y, b23.x, b23.y};
#pragma unroll
            for (int i = 0; i < 8; i++) {
                unsigned long long ai = pack2(a[i], a[i]);
#pragma unroll
                for (int j = 0; j < 4; j++) fma2(acc[i][j], ai, bp[j]);
            }
        }
    }

    __syncthreads();   // everyone done reading As/Bs; SM reusable

    int jb = tx * 8;
#pragma unroll
    for (int i = 0; i < 8; i++) {
        int node = ty * 8 + i;
        int m = m0 + node;
        if (m >= N_NODES) continue;
        float av[8];
#pragma unroll
        for (int j = 0; j < 4; j++) {
            float2 p = unpack2(acc[i][j]);
            av[2 * j] = p.x; av[2 * j + 1] = p.y;
        }
        if (jb < 64) {
            float o[8];
#pragma unroll
            for (int j = 0; j < 8; j++) o[j] = fast_tanh(av[j] + bias_s[jb + j]);
            float4* p = reinterpret_cast<float4*>(g_h1 + (size_t)m * 64 + jb);
            p[0] = make_float4(o[0], o[1], o[2], o[3]);
            p[1] = make_float4(o[4], o[5], o[6], o[7]);
            float4* tp = reinterpret_cast<float4*>(&SM[node * 68 + jb]);
            tp[0] = make_float4(o[0], o[1], o[2], o[3]);
            tp[1] = make_float4(o[4], o[5], o[6], o[7]);
        } else {
            union { __half2 h[4]; uint4 u; } pk;
#pragma unroll
            for (int p = 0; p < 4; p++) {
                float va = av[2 * p]     + bias_s[jb + 2 * p];
                float vb = av[2 * p + 1] + bias_s[jb + 2 * p + 1];
                pk.h[p] = __floats2half2_rn(va, vb);
            }
            *reinterpret_cast<uint4*>(g_xs + (size_t)m * 64 + (jb - 64)) = pk.u;
        }
    }
    __syncthreads();   // T complete

    float* W1s = SM + 8704;
    for (int i = tid; i < 2048; i += 256) W1s[i] = att_w1[i];
    __syncthreads();

    int node = tid >> 1;
    int j0 = (tid & 1) * 16;
    float part = 0.f;
    if (m0 + node < N_NODES) {
        float s[16];
#pragma unroll
        for (int jj = 0; jj < 16; jj++) s[jj] = b1s[j0 + jj];
        for (int k = 0; k < 64; k += 4) {
            float4 h4 = *reinterpret_cast<const float4*>(&SM[node * 68 + k]);
            float h[4] = {h4.x, h4.y, h4.z, h4.w};
#pragma unroll
            for (int kk = 0; kk < 4; kk++) {
                const float4* wrow = reinterpret_cast<const float4*>(&W1s[(k + kk) * 32 + j0]);
#pragma unroll
                for (int jv = 0; jv < 4; jv++) {
                    float4 w = wrow[jv];
                    s[jv * 4 + 0] = fmaf(h[kk], w.x, s[jv * 4 + 0]);
                    s[jv * 4 + 1] = fmaf(h[kk], w.y, s[jv * 4 + 1]);
                    s[jv * 4 + 2] = fmaf(h[kk], w.z, s[jv * 4 + 2]);
                    s[jv * 4 + 3] = fmaf(h[kk], w.w, s[jv * 4 + 3]);
                }
            }
        }
#pragma unroll
        for (int jj = 0; jj < 16; jj++) part += fast_tanh(s[jj]) * w2s[j0 + jj];
    }
#pragma unroll
    for (int off = 16; off > 0; off >>= 1)
        part += __shfl_down_sync(0xffffffff, part, off);
    if ((tid & 31) == 0) redbuf[tid >> 5] = part;
    __syncthreads();
    if (tid == 0) {
        float sum = 0.f;
#pragma unroll
        for (int w = 0; w < 8; w++) sum += redbuf[w];
        atomicAdd(&g_wpart[0][blockIdx.x & 15], sum);
    }
}

// ---------------- warp-per-node CSR aggregation (plain, R10/R14 config) ----------------
__global__ __launch_bounds__(256) void k_agg() {
    int tid = threadIdx.x;
    int warp = tid >> 5, lane = tid & 31;
    int n = blockIdx.x * 8 + warp;
    if (n >= N_NODES) return;

    int beg = g_rowstart[n];
    int deg = g_deg_in[n];
    int end = beg + deg;

    float2 acc = make_float2(0.f, 0.f);
    const __half2* xsh = reinterpret_cast<const __half2*>(g_xs);
    int e = beg;
    int end8 = beg + (deg & ~7);
    for (; e < end8; e += 8) {
        int s[8];
#pragma unroll
        for (int u = 0; u < 8; u++) s[u] = __ldg(&g_csr[e + u]);
        float w[8];
#pragma unroll
        for (int u = 0; u < 8; u++) w[u] = __ldg(&g_inv_out[s[u]]);
        float2 f[8];
#pragma unroll
        for (int u = 0; u < 8; u++)
            f[u] = __half22float2(__ldg(&xsh[(size_t)s[u] * 32 + lane]));
#pragma unroll
        for (int u = 0; u < 8; u++) {
            acc.x = fmaf(f[u].x, w[u], acc.x);
            acc.y = fmaf(f[u].y, w[u], acc.y);
        }
    }
    for (; e < end; e++) {
        int s0 = __ldg(&g_csr[e]);
        float w0 = __ldg(&g_inv_out[s0]);
        float2 f0 = __half22float2(__ldg(&xsh[(size_t)s0 * 32 + lane]));
        acc.x = fmaf(f0.x, w0, acc.x);
        acc.y = fmaf(f0.y, w0, acc.y);
    }
    float sc = rsqrtf(fmaxf((float)deg, 1.f));
    acc.x *= sc; acc.y *= sc;
    reinterpret_cast<float2*>(g_h2)[(size_t)n * 32 + lane] = acc;
}

// ---------------- ch-1 attention (256 threads, 256 nodes/block for occupancy) ------------
__global__ __launch_bounds__(256) void k_att(const float* __restrict__ att_w1,
                                             const float* __restrict__ att_b1,
                                             const float* __restrict__ att_w2) {
    __shared__ float Ws[64][32];     // 8KB
    __shared__ float As[8][256];     // 8KB
    __shared__ float b1s[32], w2s[32];
    __shared__ float redbuf[8];

    int tid = threadIdx.x;
    int m0  = blockIdx.x * 256;

    for (int i = tid; i < 64 * 32; i += 256) ((float*)Ws)[i] = att_w1[i];
    if (tid < 32) { b1s[tid] = att_b1[tid]; w2s[tid] = att_w2[tid]; }

    int tx = tid & 7, ty = tid >> 3;   // 8 col-groups of 4, 32 node-groups of 8

    int m_load = m0 + tid;
    bool valid = m_load < N_NODES;
    const float4* hrow = reinterpret_cast<const float4*>(g_h2 + (size_t)m_load * 64);
    float4 z4 = make_float4(0.f, 0.f, 0.f, 0.f);

    float acc[8][4];
#pragma unroll
    for (int i = 0; i < 8; i++)
#pragma unroll
        for (int j = 0; j < 4; j++) acc[i][j] = 0.f;

    for (int kc = 0; kc < 64; kc += 8) {
        __syncthreads();
        float4 v0 = valid ? hrow[kc >> 2]       : z4;
        float4 v1 = valid ? hrow[(kc >> 2) + 1] : z4;
        As[0][tid] = v0.x; As[1][tid] = v0.y; As[2][tid] = v0.z; As[3][tid] = v0.w;
        As[4][tid] = v1.x; As[5][tid] = v1.y; As[6][tid] = v1.z; As[7][tid] = v1.w;
        __syncthreads();

#pragma unroll
        for (int k = 0; k < 8; k++) {
            float4 a0 = *reinterpret_cast<const float4*>(&As[k][ty * 8]);
            float4 a1 = *reinterpret_cast<const float4*>(&As[k][ty * 8 + 4]);
            float4 b  = *reinterpret_cast<const float4*>(&Ws[kc + k][tx * 4]);
            float a[8] = {a0.x, a0.y, a0.z, a0.w, a1.x, a1.y, a1.z, a1.w};
            float bb[4] = {b.x, b.y, b.z, b.w};
#pragma unroll
            for (int i = 0; i < 8; i++)
#pragma unroll
                for (int j = 0; j < 4; j++) acc[i][j] += a[i] * bb[j];
        }
    }

    float part = 0.f;
#pragma unroll
    for (int i = 0; i < 8; i++) {
        int m = m0 + ty * 8 + i;
        if (m >= N_NODES) continue;
#pragma unroll
        for (int j = 0; j < 4; j++)
            part += fast_tanh(acc[i][j] + b1s[tx * 4 + j]) * w2s[tx * 4 + j];
    }
#pragma unroll
    for (int off = 16; off > 0; off >>= 1)
        part += __shfl_down_sync(0xffffffff, part, off);
    if ((tid & 31) == 0) redbuf[tid >> 5] = part;
    __syncthreads();
    if (tid == 0) {
        float s = 0.f;
#pragma unroll
        for (int w = 0; w < 8; w++) s += redbuf[w];
        atomicAdd(&g_wpart[1][blockIdx.x & 15], s);
    }
}

// ---------------- final: beta softmax, blend, fc2 ----------------
__global__ __launch_bounds__(256) void k_out(const float* __restrict__ fc2_w,
                                             const float* __restrict__ fc2_b,
                                             float* __restrict__ out) {
    __shared__ float4 ws[16 * 16];
    __shared__ float bs[16];

    int tid = threadIdx.x;
    for (int i = tid; i < 16 * 16; i += 256)
        ws[i] = reinterpret_cast<const float4*>(fc2_w)[i];
    if (tid < 16) bs[tid] = fc2_b[tid];
    __syncthreads();

    int n = blockIdx.x * blockDim.x + tid;
    if (n >= N_NODES) return;

    float s0 = 0.f, s1 = 0.f;
#pragma unroll
    for (int i = 0; i < 16; i++) { s0 += g_wpart[0][i]; s1 += g_wpart[1][i]; }
    float m0 = s0 * (1.f / N_NODES);
    float m1 = s1 * (1.f / N_NODES);
    float mx = fmaxf(m0, m1);
    float e0 = expf(m0 - mx), e1 = expf(m1 - mx);
    float inv = 1.f / (e0 + e1);
    float b0 = e0 * inv, b1 = e1 * inv;

    const float4* r1 = reinterpret_cast<const float4*>(g_h1 + (size_t)n * 64);
    const float4* r2 = reinterpret_cast<const float4*>(g_h2 + (size_t)n * 64);
    float4 f[16];
#pragma unroll
    for (int i = 0; i < 16; i++) {
        float4 a = r1[i], b = r2[i];
        f[i] = make_float4(b0 * a.x + b1 * b.x, b0 * a.y + b1 * b.y,
                           b0 * a.z + b1 * b.z, b0 * a.w + b1 * b.w);
    }
    float o[16];
#pragma unroll
    for (int j = 0; j < 16; j++) {
        float acc = bs[j];
#pragma unroll
        for (int i = 0; i < 16; i++) {
            float4 w = ws[j * 16 + i];
            acc += f[i].x * w.x + f[i].y * w.y + f[i].z * w.z + f[i].w * w.w;
        }
        o[j] = acc;
    }
    float4* orow = reinterpret_cast<float4*>(out + (size_t)n * 16);
#pragma unroll
    for (int j = 0; j < 4; j++)
        orow[j] = make_float4(o[j * 4], o[j * 4 + 1], o[j * 4 + 2], o[j * 4 + 3]);
}

// ---------------- launch: R14 fork-join; ch-0 fused in gemm, ch-1 separate ----------------
extern "C" void kernel_launch(void* const* d_in, const int* in_sizes, int n_in,
                              void* d_out, int out_size)
{
    const float* feat   = (const float*)d_in[0];
    const int*   e_src  = (const int*)  d_in[1];
    const int*   e_dst  = (const int*)  d_in[2];
    const float* fc1_w  = (const float*)d_in[3];
    const float* fc1_b  = (const float*)d_in[4];
    const float* filt_w = (const float*)d_in[5];
    const float* filt_b = (const float*)d_in[6];
    const float* att_w1 = (const float*)d_in[7];
    const float* att_b1 = (const float*)d_in[8];
    const float* att_w2 = (const float*)d_in[9];
    const float* fc2_w  = (const float*)d_in[10];
    const float* fc2_b  = (const float*)d_in[11];
    float* out = (float*)d_out;

    static cudaStream_t s1 = nullptr;
    static cudaEvent_t ev_fork = nullptr, ev_gemm = nullptr;
    if (!s1) {
        cudaStreamCreateWithFlags(&s1, cudaStreamNonBlocking);
        cudaEventCreateWithFlags(&ev_fork, cudaEventDisableTiming);
        cudaEventCreateWithFlags(&ev_gemm, cudaEventDisableTiming);
    }
    cudaStream_t s0 = (cudaStream_t)0;

    // s0: init (zeroes degrees + wpart); fork point for s1
    k_init<<<(N_NODES + 255) / 256, 256, 0, s0>>>();
    cudaEventRecord(ev_fork, s0);

    // s1: weights -> dual GEMM (+fused ch-0 attention)
    cudaStreamWaitEvent(s1, ev_fork, 0);
    k_prepW<<<(64 * 128 + 255) / 256, 256, 0, s1>>>(fc1_w, fc1_b, filt_w, filt_b);
    k_gemm<<<(N_NODES + 127) / 128, 256, 0, s1>>>(feat, att_w1, att_b1, att_w2);
    cudaEventRecord(ev_gemm, s1);

    // s0: graph chain — degrees -> scan(+inv_out) -> CSR (overlaps s1)
    k_degree<<<(N_EDGES / 4 + 255) / 256, 256, 0, s0>>>((const int4*)e_src, (const int4*)e_dst);
    k_scan1<<<NB_SCAN, 256, 0, s0>>>();
    k_scan2<<<1, 512, 0, s0>>>();
    k_scan3<<<(N_NODES + 255) / 256, 256, 0, s0>>>();
    k_csr<<<(N_EDGES + 255) / 256, 256, 0, s0>>>(e_src, e_dst);

    // join: aggregation needs CSR+inv_out (s0) and xs (gemm, s1)
    cudaStreamWaitEvent(s0, ev_gemm, 0);
    k_agg<<<(N_NODES + 7) / 8, 256, 0, s0>>>();

    // ch-1 attention on h2 (256-node tiles, 256 threads)
    k_att<<<(N_NODES + 255) / 256, 256, 0, s0>>>(att_w1, att_b1, att_w2);

    // blend + fc2
    k_out<<<(N_NODES + 255) / 256, 256, 0, s0>>>(fc2_w, fc2_b, out);
}

// round 17
// speedup vs baseline: 1.1052x; 1.0307x over previous
#include <cuda_runtime.h>
#include <cuda_fp16.h>
#include <math.h>

#define N_NODES 100000
#define N_EDGES 1600000
#define NB_SCAN 391   // ceil(100000/256)

// ---------------- scratch (device globals) ----------------
__device__ float  g_h1[(size_t)N_NODES * 64];   // tanh MLP branch (fp32)
__device__ __half g_xs[(size_t)N_NODES * 64];   // filter linear out (UNscaled, fp16)
__device__ float  g_h2[(size_t)N_NODES * 64];   // aggregated branch (inv_in applied)
__device__ int    g_deg_out[N_NODES];
__device__ int    g_deg_in [N_NODES];
__device__ float  g_inv_out[N_NODES];
__device__ int    g_rowstart[N_NODES];
__device__ int    g_cursor[N_NODES];
__device__ int    g_part[512];
__device__ int    g_csr[N_EDGES];
__device__ float  g_W[64 * 128];                // fused [k][j]: j<64 fc1, j>=64 filt
__device__ float  g_bias[128];
__device__ float  g_wpart[2][16];               // attention logit partial sums

__device__ __forceinline__ float fast_tanh(float x) {
    float e = __expf(2.f * x);
    return 1.f - __fdividef(2.f, e + 1.f);
}

// ---- packed f32x2 helpers (sm_103a) ----
__device__ __forceinline__ unsigned long long pack2(float lo, float hi) {
    unsigned long long r;
    asm("mov.b64 %0, {%1, %2};" : "=l"(r) : "f"(lo), "f"(hi));
    return r;
}
__device__ __forceinline__ float2 unpack2(unsigned long long v) {
    float2 r;
    asm("mov.b64 {%0, %1}, %2;" : "=f"(r.x), "=f"(r.y) : "l"(v));
    return r;
}
__device__ __forceinline__ void fma2(unsigned long long& d, unsigned long long a,
                                     unsigned long long b) {
    asm("fma.rn.f32x2 %0, %1, %2, %0;" : "+l"(d) : "l"(a), "l"(b));
}

// ---------------- zero scratch ----------------
__global__ void k_init() {
    int i = blockIdx.x * blockDim.x + threadIdx.x;
    if (i < N_NODES) { g_deg_out[i] = 0; g_deg_in[i] = 0; }
    if (i < 32) g_wpart[i >> 4][i & 15] = 0.f;
}

// ---------------- degree histogram (4 edges / thread) ----------------
__global__ void k_degree(const int4* __restrict__ src4, const int4* __restrict__ dst4) {
    int i = blockIdx.x * blockDim.x + threadIdx.x;
    if (i >= N_EDGES / 4) return;
    int4 s = __ldg(&src4[i]);
    int4 d = __ldg(&dst4[i]);
    atomicAdd(&g_deg_out[s.x], 1); atomicAdd(&g_deg_out[s.y], 1);
    atomicAdd(&g_deg_out[s.z], 1); atomicAdd(&g_deg_out[s.w], 1);
    atomicAdd(&g_deg_in[d.x], 1);  atomicAdd(&g_deg_in[d.y], 1);
    atomicAdd(&g_deg_in[d.z], 1);  atomicAdd(&g_deg_in[d.w], 1);
}

// ---------------- weight prep (no degree dependency) ----------------
__global__ void k_prepW(const float* __restrict__ fc1_w, const float* __restrict__ fc1_b,
                        const float* __restrict__ filt_w, const float* __restrict__ filt_b) {
    int i = blockIdx.x * blockDim.x + threadIdx.x;
    if (i < 64 * 128) {
        int k = i >> 7, j = i & 127;
        g_W[i] = (j < 64) ? fc1_w[j * 64 + k] : filt_w[(j - 64) * 64 + k];
    }
    if (i < 128) g_bias[i] = (i < 64) ? fc1_b[i] : filt_b[i - 64];
}

// ---------------- exclusive scan of deg_in (inv_out folded into stage 3) --------
__global__ void k_scan1() {
    __shared__ int sh[256];
    int t = threadIdx.x;
    int i = blockIdx.x * 256 + t;
    int v = (i < N_NODES) ? g_deg_in[i] : 0;
    sh[t] = v;
    __syncthreads();
#pragma unroll
    for (int off = 1; off < 256; off <<= 1) {
        int add = (t >= off) ? sh[t - off] : 0;
        __syncthreads();
        sh[t] += add;
        __syncthreads();
    }
    if (i < N_NODES) g_rowstart[i] = sh[t] - v;
    if (t == 255) g_part[blockIdx.x] = sh[255];
}

__global__ void k_scan2() {
    __shared__ int sh[512];
    int t = threadIdx.x;
    int v = (t < NB_SCAN) ? g_part[t] : 0;
    sh[t] = v;
    __syncthreads();
#pragma unroll
    for (int off = 1; off < 512; off <<= 1) {
        int add = (t >= off) ? sh[t - off] : 0;
        __syncthreads();
        sh[t] += add;
        __syncthreads();
    }
    if (t < NB_SCAN) g_part[t] = sh[t] - v;
}

__global__ void k_scan3() {
    int i = blockIdx.x * blockDim.x + threadIdx.x;
    if (i < N_NODES) {
        int rs = g_rowstart[i] + g_part[i >> 8];
        g_rowstart[i] = rs;
        g_cursor[i]   = rs;
        g_inv_out[i]  = rsqrtf(fmaxf((float)g_deg_out[i], 1.f));
    }
}

// ---------------- CSR build (counting sort by dst) ----------------
__global__ void k_csr(const int* __restrict__ src, const int* __restrict__ dst) {
    int e = blockIdx.x * blockDim.x + threadIdx.x;
    if (e >= N_EDGES) return;
    int d = __ldg(&dst[e]);
    int pos = atomicAdd(&g_cursor[d], 1);
    g_csr[pos] = __ldg(&src[e]);
}

// ---------------- tiled dual GEMM + FUSED ch-0 attention (R14/R16 config) ----------------
__global__ __launch_bounds__(256) void k_gemm(const float* __restrict__ feat,
                                              const float* __restrict__ att_w1,
                                              const float* __restrict__ att_b1,
                                              const float* __restrict__ att_w2) {
    __shared__ float SM[10752];
    __shared__ float bias_s[128];
    __shared__ float b1s[32], w2s[32];
    __shared__ float redbuf[8];

    float* Bs = SM;            // [64][128] during main loop
    float* As = SM + 8192;     // [16][128] during main loop

    int tid = threadIdx.x;
    int m0 = blockIdx.x * 128;

    for (int i = tid; i < 64 * 128; i += 256) Bs[i] = g_W[i];
    if (tid < 128) bias_s[tid] = g_bias[tid];
    if (tid < 32) { b1s[tid] = att_b1[tid]; w2s[tid] = att_w2[tid]; }

    int tx = tid & 15, ty = tid >> 4;
    int r  = tid & 127, hf = tid >> 7;

    unsigned long long acc[8][4];
#pragma unroll
    for (int i = 0; i < 8; i++)
#pragma unroll
        for (int j = 0; j < 4; j++) acc[i][j] = 0ull;

    int m_load = m0 + r;
    bool valid = m_load < N_NODES;
    const float4* frow = reinterpret_cast<const float4*>(feat + (size_t)m_load * 64);
    float4 z4 = make_float4(0.f, 0.f, 0.f, 0.f);

    for (int kc = 0; kc < 64; kc += 16) {
        __syncthreads();
        float4 v0 = valid ? frow[(kc >> 2) + hf * 2]     : z4;
        float4 v1 = valid ? frow[(kc >> 2) + hf * 2 + 1] : z4;
        int kb = hf * 8;
        As[(kb + 0) * 128 + r] = v0.x; As[(kb + 1) * 128 + r] = v0.y;
        As[(kb + 2) * 128 + r] = v0.z; As[(kb + 3) * 128 + r] = v0.w;
        As[(kb + 4) * 128 + r] = v1.x; As[(kb + 5) * 128 + r] = v1.y;
        As[(kb + 6) * 128 + r] = v1.z; As[(kb + 7) * 128 + r] = v1.w;
        __syncthreads();

#pragma unroll
        for (int k = 0; k < 16; k++) {
            float4 a0 = *reinterpret_cast<const float4*>(&As[k * 128 + ty * 8]);
            float4 a1 = *reinterpret_cast<const float4*>(&As[k * 128 + ty * 8 + 4]);
            ulonglong2 b01 = *reinterpret_cast<const ulonglong2*>(&Bs[(kc + k) * 128 + tx * 8]);
            ulonglong2 b23 = *reinterpret_cast<const ulonglong2*>(&Bs[(kc + k) * 128 + tx * 8 + 4]);
            float a[8] = {a0.x, a0.y, a0.z, a0.w, a1.x, a1.y, a1.z, a1.w};
            unsigned long long bp[4] = {b01.x, b01.y, b23.x, b23.y};
#pragma unroll
            for (int i = 0; i < 8; i++) {
                unsigned long long ai = pack2(a[i], a[i]);
#pragma unroll
                for (int j = 0; j < 4; j++) fma2(acc[i][j], ai, bp[j]);
            }
        }
    }

    __syncthreads();

    int jb = tx * 8;
#pragma unroll
    for (int i = 0; i < 8; i++) {
        int node = ty * 8 + i;
        int m = m0 + node;
        if (m >= N_NODES) continue;
        float av[8];
#pragma unroll
        for (int j = 0; j < 4; j++) {
            float2 p = unpack2(acc[i][j]);
            av[2 * j] = p.x; av[2 * j + 1] = p.y;
        }
        if (jb < 64) {
            float o[8];
#pragma unroll
            for (int j = 0; j < 8; j++) o[j] = fast_tanh(av[j] + bias_s[jb + j]);
            float4* p = reinterpret_cast<float4*>(g_h1 + (size_t)m * 64 + jb);
            p[0] = make_float4(o[0], o[1], o[2], o[3]);
            p[1] = make_float4(o[4], o[5], o[6], o[7]);
            float4* tp = reinterpret_cast<float4*>(&SM[node * 68 + jb]);
            tp[0] = make_float4(o[0], o[1], o[2], o[3]);
            tp[1] = make_float4(o[4], o[5], o[6], o[7]);
        } else {
            union { __half2 h[4]; uint4 u; } pk;
#pragma unroll
            for (int p = 0; p < 4; p++) {
                float va = av[2 * p]     + bias_s[jb + 2 * p];
                float vb = av[2 * p + 1] + bias_s[jb + 2 * p + 1];
                pk.h[p] = __floats2half2_rn(va, vb);
            }
            *reinterpret_cast<uint4*>(g_xs + (size_t)m * 64 + (jb - 64)) = pk.u;
        }
    }
    __syncthreads();

    float* W1s = SM + 8704;
    for (int i = tid; i < 2048; i += 256) W1s[i] = att_w1[i];
    __syncthreads();

    int node = tid >> 1;
    int j0 = (tid & 1) * 16;
    float part = 0.f;
    if (m0 + node < N_NODES) {
        float s[16];
#pragma unroll
        for (int jj = 0; jj < 16; jj++) s[jj] = b1s[j0 + jj];
        for (int k = 0; k < 64; k += 4) {
            float4 h4 = *reinterpret_cast<const float4*>(&SM[node * 68 + k]);
            float h[4] = {h4.x, h4.y, h4.z, h4.w};
#pragma unroll
            for (int kk = 0; kk < 4; kk++) {
                const float4* wrow = reinterpret_cast<const float4*>(&W1s[(k + kk) * 32 + j0]);
#pragma unroll
                for (int jv = 0; jv < 4; jv++) {
                    float4 w = wrow[jv];
                    s[jv * 4 + 0] = fmaf(h[kk], w.x, s[jv * 4 + 0]);
                    s[jv * 4 + 1] = fmaf(h[kk], w.y, s[jv * 4 + 1]);
                    s[jv * 4 + 2] = fmaf(h[kk], w.z, s[jv * 4 + 2]);
                    s[jv * 4 + 3] = fmaf(h[kk], w.w, s[jv * 4 + 3]);
                }
            }
        }
#pragma unroll
        for (int jj = 0; jj < 16; jj++) part += fast_tanh(s[jj]) * w2s[j0 + jj];
    }
#pragma unroll
    for (int off = 16; off > 0; off >>= 1)
        part += __shfl_down_sync(0xffffffff, part, off);
    if ((tid & 31) == 0) redbuf[tid >> 5] = part;
    __syncthreads();
    if (tid == 0) {
        float sum = 0.f;
#pragma unroll
        for (int w = 0; w < 8; w++) sum += redbuf[w];
        atomicAdd(&g_wpart[0][blockIdx.x & 15], sum);
    }
}

// ---------------- CSR aggregation: half-warp split, 2 edges per load (2x MLP) ------------
__global__ __launch_bounds__(256) void k_agg() {
    int tid = threadIdx.x;
    int warp = tid >> 5, lane = tid & 31;
    int half = lane >> 4;           // 0: even edges, 1: odd edges
    int sub  = lane & 15;           // column group (4 halves = 8 bytes)
    int n = blockIdx.x * 8 + warp;
    if (n >= N_NODES) return;

    int beg = g_rowstart[n];
    int deg = g_deg_in[n];
    int end = beg + deg;

    float4 acc = make_float4(0.f, 0.f, 0.f, 0.f);
    const uint2* xs8 = reinterpret_cast<const uint2*>(g_xs);   // row = 16 x 8B

    int e = beg;
    int end16 = beg + (deg & ~15);
    for (; e < end16; e += 16) {
        int s[8];
#pragma unroll
        for (int u = 0; u < 8; u++) s[u] = __ldg(&g_csr[e + 2 * u + half]);
        float w[8];
#pragma unroll
        for (int u = 0; u < 8; u++) w[u] = __ldg(&g_inv_out[s[u]]);
        uint2 q[8];
#pragma unroll
        for (int u = 0; u < 8; u++) q[u] = __ldg(&xs8[(size_t)s[u] * 16 + sub]);
#pragma unroll
        for (int u = 0; u < 8; u++) {
            float2 f0 = __half22float2(*reinterpret_cast<__half2*>(&q[u].x));
            float2 f1 = __half22float2(*reinterpret_cast<__half2*>(&q[u].y));
            acc.x = fmaf(f0.x, w[u], acc.x);
            acc.y = fmaf(f0.y, w[u], acc.y);
            acc.z = fmaf(f1.x, w[u], acc.z);
            acc.w = fmaf(f1.y, w[u], acc.w);
        }
    }
    // pair remainder (2 edges at a time)
    for (; e + 1 < end; e += 2) {
        int s0 = __ldg(&g_csr[e + half]);
        float w0 = __ldg(&g_inv_out[s0]);
        uint2 q = __ldg(&xs8[(size_t)s0 * 16 + sub]);
        float2 f0 = __half22float2(*reinterpret_cast<__half2*>(&q.x));
        float2 f1 = __half22float2(*reinterpret_cast<__half2*>(&q.y));
        acc.x = fmaf(f0.x, w0, acc.x);
        acc.y = fmaf(f0.y, w0, acc.y);
        acc.z = fmaf(f1.x, w0, acc.z);
        acc.w = fmaf(f1.y, w0, acc.w);
    }
    // single leftover edge: only half 0 accumulates
    if (e < end && half == 0) {
        int s0 = __ldg(&g_csr[e]);
        float w0 = __ldg(&g_inv_out[s0]);
        uint2 q = __ldg(&xs8[(size_t)s0 * 16 + sub]);
        float2 f0 = __half22float2(*reinterpret_cast<__half2*>(&q.x));
        float2 f1 = __half22float2(*reinterpret_cast<__half2*>(&q.y));
        acc.x = fmaf(f0.x, w0, acc.x);
        acc.y = fmaf(f0.y, w0, acc.y);
        acc.z = fmaf(f1.x, w0, acc.z);
        acc.w = fmaf(f1.y, w0, acc.w);
    }

    // combine halves: lane sub += lane sub+16
    acc.x += __shfl_down_sync(0xffffffff, acc.x, 16);
    acc.y += __shfl_down_sync(0xffffffff, acc.y, 16);
    acc.z += __shfl_down_sync(0xffffffff, acc.z, 16);
    acc.w += __shfl_down_sync(0xffffffff, acc.w, 16);

    if (half == 0) {
        float sc = rsqrtf(fmaxf((float)deg, 1.f));
        acc.x *= sc; acc.y *= sc; acc.z *= sc; acc.w *= sc;
        reinterpret_cast<float4*>(g_h2)[(size_t)n * 16 + sub] = acc;
    }
}

// ---------------- ch-1 attention (256 threads, 256 nodes/block — R16 config) ------------
__global__ __launch_bounds__(256) void k_att(const float* __restrict__ att_w1,
                                             const float* __restrict__ att_b1,
                                             const float* __restrict__ att_w2) {
    __shared__ float Ws[64][32];
    __shared__ float As[8][256];
    __shared__ float b1s[32], w2s[32];
    __shared__ float redbuf[8];

    int tid = threadIdx.x;
    int m0  = blockIdx.x * 256;

    for (int i = tid; i < 64 * 32; i += 256) ((float*)Ws)[i] = att_w1[i];
    if (tid < 32) { b1s[tid] = att_b1[tid]; w2s[tid] = att_w2[tid]; }

    int tx = tid & 7, ty = tid >> 3;

    int m_load = m0 + tid;
    bool valid = m_load < N_NODES;
    const float4* hrow = reinterpret_cast<const float4*>(g_h2 + (size_t)m_load * 64);
    float4 z4 = make_float4(0.f, 0.f, 0.f, 0.f);

    float acc[8][4];
#pragma unroll
    for (int i = 0; i < 8; i++)
#pragma unroll
        for (int j = 0; j < 4; j++) acc[i][j] = 0.f;

    for (int kc = 0; kc < 64; kc += 8) {
        __syncthreads();
        float4 v0 = valid ? hrow[kc >> 2]       : z4;
        float4 v1 = valid ? hrow[(kc >> 2) + 1] : z4;
        As[0][tid] = v0.x; As[1][tid] = v0.y; As[2][tid] = v0.z; As[3][tid] = v0.w;
        As[4][tid] = v1.x; As[5][tid] = v1.y; As[6][tid] = v1.z; As[7][tid] = v1.w;
        __syncthreads();

#pragma unroll
        for (int k = 0; k < 8; k++) {
            float4 a0 = *reinterpret_cast<const float4*>(&As[k][ty * 8]);
            float4 a1 = *reinterpret_cast<const float4*>(&As[k][ty * 8 + 4]);
            float4 b  = *reinterpret_cast<const float4*>(&Ws[kc + k][tx * 4]);
            float a[8] = {a0.x, a0.y, a0.z, a0.w, a1.x, a1.y, a1.z, a1.w};
            float bb[4] = {b.x, b.y, b.z, b.w};
#pragma unroll
            for (int i = 0; i < 8; i++)
#pragma unroll
                for (int j = 0; j < 4; j++) acc[i][j] += a[i] * bb[j];
        }
    }

    float part = 0.f;
#pragma unroll
    for (int i = 0; i < 8; i++) {
        int m = m0 + ty * 8 + i;
        if (m >= N_NODES) continue;
#pragma unroll
        for (int j = 0; j < 4; j++)
            part += fast_tanh(acc[i][j] + b1s[tx * 4 + j]) * w2s[tx * 4 + j];
    }
#pragma unroll
    for (int off = 16; off > 0; off >>= 1)
        part += __shfl_down_sync(0xffffffff, part, off);
    if ((tid & 31) == 0) redbuf[tid >> 5] = part;
    __syncthreads();
    if (tid == 0) {
        float s = 0.f;
#pragma unroll
        for (int w = 0; w < 8; w++) s += redbuf[w];
        atomicAdd(&g_wpart[1][blockIdx.x & 15], s);
    }
}

// ---------------- final: beta softmax, blend, fc2 ----------------
__global__ __launch_bounds__(256) void k_out(const float* __restrict__ fc2_w,
                                             const float* __restrict__ fc2_b,
                                             float* __restrict__ out) {
    __shared__ float4 ws[16 * 16];
    __shared__ float bs[16];

    int tid = threadIdx.x;
    for (int i = tid; i < 16 * 16; i += 256)
        ws[i] = reinterpret_cast<const float4*>(fc2_w)[i];
    if (tid < 16) bs[tid] = fc2_b[tid];
    __syncthreads();

    int n = blockIdx.x * blockDim.x + tid;
    if (n >= N_NODES) return;

    float s0 = 0.f, s1 = 0.f;
#pragma unroll
    for (int i = 0; i < 16; i++) { s0 += g_wpart[0][i]; s1 += g_wpart[1][i]; }
    float m0 = s0 * (1.f / N_NODES);
    float m1 = s1 * (1.f / N_NODES);
    float mx = fmaxf(m0, m1);
    float e0 = expf(m0 - mx), e1 = expf(m1 - mx);
    float inv = 1.f / (e0 + e1);
    float b0 = e0 * inv, b1 = e1 * inv;

    const float4* r1 = reinterpret_cast<const float4*>(g_h1 + (size_t)n * 64);
    const float4* r2 = reinterpret_cast<const float4*>(g_h2 + (size_t)n * 64);
    float4 f[16];
#pragma unroll
    for (int i = 0; i < 16; i++) {
        float4 a = r1[i], b = r2[i];
        f[i] = make_float4(b0 * a.x + b1 * b.x, b0 * a.y + b1 * b.y,
                           b0 * a.z + b1 * b.z, b0 * a.w + b1 * b.w);
    }
    float o[16];
#pragma unroll
    for (int j = 0; j < 16; j++) {
        float acc = bs[j];
#pragma unroll
        for (int i = 0; i < 16; i++) {
            float4 w = ws[j * 16 + i];
            acc += f[i].x * w.x + f[i].y * w.y + f[i].z * w.z + f[i].w * w.w;
        }
        o[j] = acc;
    }
    float4* orow = reinterpret_cast<float4*>(out + (size_t)n * 16);
#pragma unroll
    for (int j = 0; j < 4; j++)
        orow[j] = make_float4(o[j * 4], o[j * 4 + 1], o[j * 4 + 2], o[j * 4 + 3]);
}

// ---------------- launch: R16 fork-join ----------------
extern "C" void kernel_launch(void* const* d_in, const int* in_sizes, int n_in,
                              void* d_out, int out_size)
{
    const float* feat   = (const float*)d_in[0];
    const int*   e_src  = (const int*)  d_in[1];
    const int*   e_dst  = (const int*)  d_in[2];
    const float* fc1_w  = (const float*)d_in[3];
    const float* fc1_b  = (const float*)d_in[4];
    const float* filt_w = (const float*)d_in[5];
    const float* filt_b = (const float*)d_in[6];
    const float* att_w1 = (const float*)d_in[7];
    const float* att_b1 = (const float*)d_in[8];
    const float* att_w2 = (const float*)d_in[9];
    const float* fc2_w  = (const float*)d_in[10];
    const float* fc2_b  = (const float*)d_in[11];
    float* out = (float*)d_out;

    static cudaStream_t s1 = nullptr;
    static cudaEvent_t ev_fork = nullptr, ev_gemm = nullptr;
    if (!s1) {
        cudaStreamCreateWithFlags(&s1, cudaStreamNonBlocking);
        cudaEventCreateWithFlags(&ev_fork, cudaEventDisableTiming);
        cudaEventCreateWithFlags(&ev_gemm, cudaEventDisableTiming);
    }
    cudaStream_t s0 = (cudaStream_t)0;

    k_init<<<(N_NODES + 255) / 256, 256, 0, s0>>>();
    cudaEventRecord(ev_fork, s0);

    cudaStreamWaitEvent(s1, ev_fork, 0);
    k_prepW<<<(64 * 128 + 255) / 256, 256, 0, s1>>>(fc1_w, fc1_b, filt_w, filt_b);
    k_gemm<<<(N_NODES + 127) / 128, 256, 0, s1>>>(feat, att_w1, att_b1, att_w2);
    cudaEventRecord(ev_gemm, s1);

    k_degree<<<(N_EDGES / 4 + 255) / 256, 256, 0, s0>>>((const int4*)e_src, (const int4*)e_dst);
    k_scan1<<<NB_SCAN, 256, 0, s0>>>();
    k_scan2<<<1, 512, 0, s0>>>();
    k_scan3<<<(N_NODES + 255) / 256, 256, 0, s0>>>();
    k_csr<<<(N_EDGES + 255) / 256, 256, 0, s0>>>(e_src, e_dst);

    cudaStreamWaitEvent(s0, ev_gemm, 0);
    k_agg<<<(N_NODES + 7) / 8, 256, 0, s0>>>();

    k_att<<<(N_NODES + 255) / 256, 256, 0, s0>>>(att_w1, att_b1, att_w2);

    k_out<<<(N_NODES + 255) / 256, 256, 0, s0>>>(fc2_w, fc2_b, out);
}